// round 4
// baseline (speedup 1.0000x reference)
#include <cuda_runtime.h>

#define NN 100000
#define NE 1200000
#define DD 64
#define NBLK 391          // ceil(NN/256)
#define TILE 64
#define GRID_FUSED 1563   // ceil(NN/64)

typedef unsigned long long ull;

// scratch (__device__ globals per allocation rules)
__device__ int g_count[NN];
__device__ int g_off[NN];
__device__ int g_cur[NN];
__device__ ull g_edata[NE];     // packed {w_bits, src}
__device__ int g_total;

// ---- f32x2 helpers (sm_103a packed fp32) ----
__device__ __forceinline__ ull pk(float lo, float hi) {
    ull r; asm("mov.b64 %0, {%1, %2};" : "=l"(r) : "f"(lo), "f"(hi)); return r;
}
__device__ __forceinline__ void unpk(float& lo, float& hi, ull v) {
    asm("mov.b64 {%0, %1}, %2;" : "=f"(lo), "=f"(hi) : "l"(v));
}
__device__ __forceinline__ void fma2(ull& d, ull a, ull b) {
    asm("fma.rn.f32x2 %0, %1, %2, %0;" : "+l"(d) : "l"(a), "l"(b));
}
__device__ __forceinline__ ull mul2(ull a, ull b) {
    ull r; asm("mul.rn.f32x2 %0, %1, %2;" : "=l"(r) : "l"(a), "l"(b)); return r;
}
__device__ __forceinline__ void lds2u64(ull& a, ull& b, const float* p) {
    unsigned ad = (unsigned)__cvta_generic_to_shared(p);
    asm volatile("ld.shared.v2.u64 {%0, %1}, [%2];" : "=l"(a), "=l"(b) : "r"(ad));
}

__global__ void __launch_bounds__(256) zero_kernel() {
    int i = blockIdx.x * 256 + threadIdx.x;
    if (i < NN) g_count[i] = 0;
    if (i == 0) g_total = 0;
}

__global__ void __launch_bounds__(256) hist_kernel(const int* __restrict__ dst) {
    unsigned e = blockIdx.x * 256u + threadIdx.x;
    if (e < NE) atomicAdd(&g_count[__ldg(dst + e)], 1);
}

// Block-local scan + one global atomicAdd for the base. Segments contiguous
// and in-node-order within each aligned 256-node block; fused tiles (64 nodes,
// 64 | 256) never straddle two offset blocks, so warp edge-walks stay valid.
__global__ void __launch_bounds__(256) offsets_kernel() {
    __shared__ int arr[256];
    __shared__ int sBase;
    int t = threadIdx.x;
    int i = blockIdx.x * 256 + t;
    int c = (i < NN) ? g_count[i] : 0;
    arr[t] = c;
    __syncthreads();
    #pragma unroll
    for (int off = 1; off < 256; off <<= 1) {
        int v = (t >= off) ? arr[t - off] : 0;
        __syncthreads();
        arr[t] += v;
        __syncthreads();
    }
    if (t == 255) sBase = atomicAdd(&g_total, arr[255]);
    __syncthreads();
    if (i < NN) {
        int o = sBase + arr[t] - c;   // exclusive
        g_off[i] = o;
        g_cur[i] = o;
    }
}

__global__ void __launch_bounds__(256) fill_kernel(
    const int* __restrict__ src, const int* __restrict__ dst,
    const float* __restrict__ ew, const float* __restrict__ em) {
    unsigned e = blockIdx.x * 256u + threadIdx.x;
    if (e >= NE) return;
    int d = __ldg(dst + e);
    int s = __ldg(src + e);
    float w = __ldg(ew + e) * __ldg(em + e);
    int pos = atomicAdd(&g_cur[d], 1);
    g_edata[pos] = ((ull)(unsigned)__float_as_int(w) << 32) | (unsigned)s;
}

// Fused gather-mean + dual GEMM. 64 nodes/block, 256 threads.
// Dyn smem: sWs | sWn | sAT | sBT, 4096 floats each (64KB).
// sAT/sBT are k-major transposed with the same XOR-float4 swizzle as W.
__global__ void __launch_bounds__(256) fused_kernel(
    const float* __restrict__ feat,
    const float* __restrict__ Ws, const float* __restrict__ bs,
    const float* __restrict__ Wn, const float* __restrict__ bn,
    float* __restrict__ out) {
    extern __shared__ float smem[];
    float* sWs = smem;
    float* sWn = smem + 4096;
    float* sAT = smem + 8192;
    float* sBT = smem + 12288;
    __shared__ int sOff[TILE];
    __shared__ int sCnt[TILE];

    int t = threadIdx.x;
    int base = blockIdx.x * TILE;

    // W fill (transposed + XOR swizzle): W[j][k] -> sW[k*64 + ((j>>2)^(k&15))*4 + (j&3)]
    for (int i = t; i < DD * DD; i += 256) {
        int k = i & 63;
        int j = i >> 6;
        int sidx = k * 64 + (((j >> 2) ^ (k & 15)) << 2) + (j & 3);
        sWs[sidx] = Ws[i];
        sWn[sidx] = Wn[i];
    }

    if (t < TILE) {
        int node = base + t;
        int c = 0, o = 0;
        if (node < NN) { c = g_count[node]; o = g_off[node]; }
        sOff[t] = o;
        sCnt[t] = c;
    }

    // stage feat rows transposed+swizzled into sAT
    for (int i = t; i < TILE * 16; i += 256) {
        int n = i >> 4, cg = i & 15;
        int node = base + n;
        float4 f = (node < NN)
            ? __ldg(reinterpret_cast<const float4*>(feat) + (size_t)node * 16 + cg)
            : make_float4(0.f, 0.f, 0.f, 0.f);
        int c0 = cg * 4;
        sAT[(c0 + 0) * 64 + (((n >> 2) ^ ((c0 + 0) & 15)) << 2) + (n & 3)] = f.x;
        sAT[(c0 + 1) * 64 + (((n >> 2) ^ ((c0 + 1) & 15)) << 2) + (n & 3)] = f.y;
        sAT[(c0 + 2) * 64 + (((n >> 2) ^ ((c0 + 2) & 15)) << 2) + (n & 3)] = f.z;
        sAT[(c0 + 3) * 64 + (((n >> 2) ^ ((c0 + 3) & 15)) << 2) + (n & 3)] = f.w;
    }
    __syncthreads();

    // Phase A: gather. Warp w owns nodes [base+8w, base+8w+8); contiguous edges.
    // Lane l owns float2 chunk l of the 64-float row (row = 32 ull chunks).
    {
        int w = t >> 5, l = t & 31;
        int e = sOff[w * 8];
        const ull* f8 = reinterpret_cast<const ull*>(feat);
        const ull* ed8 = (const ull*)g_edata;
        for (int j = 0; j < 8; j++) {
            int nl = w * 8 + j;
            int cnt = sCnt[nl];
            ull acc = 0ull;   // (0.f, 0.f)
            #pragma unroll 2
            for (int i2 = 0; i2 < cnt; i2++, e++) {
                ull ed = __ldg(ed8 + e);
                int s = (int)(unsigned)(ed & 0xffffffffull);
                float wgt = __int_as_float((int)(ed >> 32));
                ull f = __ldg(f8 + (size_t)s * 32 + l);   // FIX: 32 ulls per row
                fma2(acc, f, pk(wgt, wgt));
            }
            float inv = 1.0f / fmaxf((float)cnt, 1.0f);
            acc = mul2(acc, pk(inv, inv));
            float lo, hi; unpk(lo, hi, acc);
            int c0 = 2 * l, c1 = 2 * l + 1;
            sBT[c0 * 64 + (((nl >> 2) ^ (c0 & 15)) << 2) + (nl & 3)] = lo;
            sBT[c1 * 64 + (((nl >> 2) ^ (c1 & 15)) << 2) + (nl & 3)] = hi;
        }
    }
    __syncthreads();

    // Phase B: dual GEMM with packed f32x2. thread = 4 nodes x 4 cols.
    int jg = t & 15;     // cols 4jg..4jg+3
    int ng = t >> 4;     // nodes 4ng..4ng+3 (local)
    int j0 = jg * 4;

    float b0v = __ldg(bs + j0 + 0) + __ldg(bn + j0 + 0);
    float b1v = __ldg(bs + j0 + 1) + __ldg(bn + j0 + 1);
    float b2v = __ldg(bs + j0 + 2) + __ldg(bn + j0 + 2);
    float b3v = __ldg(bs + j0 + 3) + __ldg(bn + j0 + 3);
    ull bias01 = pk(b0v, b1v), bias23 = pk(b2v, b3v);
    ull acc01[4], acc23[4];
    #pragma unroll
    for (int n = 0; n < 4; n++) { acc01[n] = bias01; acc23[n] = bias23; }

    #pragma unroll 16
    for (int k = 0; k < 64; k++) {
        int sw = k & 15;
        ull w01, w23, u01, u23;
        lds2u64(w01, w23, sWs + k * 64 + ((jg ^ sw) << 2));
        lds2u64(u01, u23, sWn + k * 64 + ((jg ^ sw) << 2));
        float4 aT = *reinterpret_cast<const float4*>(sAT + k * 64 + ((ng ^ sw) << 2));
        float4 bT = *reinterpret_cast<const float4*>(sBT + k * 64 + ((ng ^ sw) << 2));
        ull sa, sb;
        sa = pk(aT.x, aT.x); sb = pk(bT.x, bT.x);
        fma2(acc01[0], sa, w01); fma2(acc23[0], sa, w23);
        fma2(acc01[0], sb, u01); fma2(acc23[0], sb, u23);
        sa = pk(aT.y, aT.y); sb = pk(bT.y, bT.y);
        fma2(acc01[1], sa, w01); fma2(acc23[1], sa, w23);
        fma2(acc01[1], sb, u01); fma2(acc23[1], sb, u23);
        sa = pk(aT.z, aT.z); sb = pk(bT.z, bT.z);
        fma2(acc01[2], sa, w01); fma2(acc23[2], sa, w23);
        fma2(acc01[2], sb, u01); fma2(acc23[2], sb, u23);
        sa = pk(aT.w, aT.w); sb = pk(bT.w, bT.w);
        fma2(acc01[3], sa, w01); fma2(acc23[3], sa, w23);
        fma2(acc01[3], sb, u01); fma2(acc23[3], sb, u23);
    }

    #pragma unroll
    for (int n = 0; n < 4; n++) {
        int node = base + 4 * ng + n;
        if (node < NN) {
            float4 o;
            unpk(o.x, o.y, acc01[n]);
            unpk(o.z, o.w, acc23[n]);
            reinterpret_cast<float4*>(out)[(size_t)node * 16 + jg] = o;
        }
    }
}

extern "C" void kernel_launch(void* const* d_in, const int* in_sizes, int n_in,
                              void* d_out, int out_size) {
    const float* feat = (const float*)d_in[0];
    const int*   src  = (const int*)d_in[1];
    const int*   dst  = (const int*)d_in[2];
    const float* ew   = (const float*)d_in[3];
    const float* em   = (const float*)d_in[4];
    const float* Ws   = (const float*)d_in[5];
    const float* bs   = (const float*)d_in[6];
    const float* Wn   = (const float*)d_in[7];
    const float* bn   = (const float*)d_in[8];
    float* out = (float*)d_out;

    cudaFuncSetAttribute(fused_kernel,
                         cudaFuncAttributeMaxDynamicSharedMemorySize, 66560);

    zero_kernel<<<NBLK, 256>>>();
    hist_kernel<<<4688, 256>>>(dst);
    offsets_kernel<<<NBLK, 256>>>();
    fill_kernel<<<4688, 256>>>(src, dst, ew, em);
    fused_kernel<<<GRID_FUSED, 256, 65536>>>(feat, Ws, bs, Wn, bn, out);
}

// round 5
// speedup vs baseline: 1.1944x; 1.1944x over previous
#include <cuda_runtime.h>

#define NN 100000
#define NE 1200000
#define DD 64
#define NBLK 391          // ceil(NN/256)
#define GRID_FUSED 3125   // NN/32 exact

typedef unsigned long long ull;

// scratch (__device__ globals per allocation rules)
__device__ int g_count[NN];
__device__ int g_off[NN];
__device__ int g_cur[NN];
__device__ ull g_edata[NE];     // packed {w_bits, src}
__device__ int g_total;

// ---- f32x2 helpers (sm_103a packed fp32) ----
__device__ __forceinline__ ull pk(float lo, float hi) {
    ull r; asm("mov.b64 %0, {%1, %2};" : "=l"(r) : "f"(lo), "f"(hi)); return r;
}
__device__ __forceinline__ void unpk(float& lo, float& hi, ull v) {
    asm("mov.b64 {%0, %1}, %2;" : "=f"(lo), "=f"(hi) : "l"(v));
}
__device__ __forceinline__ void fma2(ull& d, ull a, ull b) {
    asm("fma.rn.f32x2 %0, %1, %2, %0;" : "+l"(d) : "l"(a), "l"(b));
}
__device__ __forceinline__ ull mul2(ull a, ull b) {
    ull r; asm("mul.rn.f32x2 %0, %1, %2;" : "=l"(r) : "l"(a), "l"(b)); return r;
}
__device__ __forceinline__ void lds2u64(ull& a, ull& b, const float* p) {
    unsigned ad = (unsigned)__cvta_generic_to_shared(p);
    asm volatile("ld.shared.v2.u64 {%0, %1}, [%2];" : "=l"(a), "=l"(b) : "r"(ad));
}

__global__ void __launch_bounds__(256) zero_kernel() {
    int i = blockIdx.x * 256 + threadIdx.x;
    if (i < NN) g_count[i] = 0;
    if (i == 0) g_total = 0;
}

// 4 edges per thread: vector load + 4 independent REDs (MLP 4)
__global__ void __launch_bounds__(256) hist_kernel(const int* __restrict__ dst) {
    unsigned g = blockIdx.x * 256u + threadIdx.x;
    if (g >= NE / 4) return;
    int4 d = __ldg(reinterpret_cast<const int4*>(dst) + g);
    atomicAdd(&g_count[d.x], 1);
    atomicAdd(&g_count[d.y], 1);
    atomicAdd(&g_count[d.z], 1);
    atomicAdd(&g_count[d.w], 1);
}

// Block-local scan + one global atomicAdd for the base.
__global__ void __launch_bounds__(256) offsets_kernel() {
    __shared__ int arr[256];
    __shared__ int sBase;
    int t = threadIdx.x;
    int i = blockIdx.x * 256 + t;
    int c = (i < NN) ? g_count[i] : 0;
    arr[t] = c;
    __syncthreads();
    #pragma unroll
    for (int off = 1; off < 256; off <<= 1) {
        int v = (t >= off) ? arr[t - off] : 0;
        __syncthreads();
        arr[t] += v;
        __syncthreads();
    }
    if (t == 255) sBase = atomicAdd(&g_total, arr[255]);
    __syncthreads();
    if (i < NN) {
        int o = sBase + arr[t] - c;   // exclusive
        g_off[i] = o;
        g_cur[i] = o;
    }
}

// 4 edges per thread: 4 independent position atomics + 4 stores (MLP 4)
__global__ void __launch_bounds__(256) fill_kernel(
    const int* __restrict__ src, const int* __restrict__ dst,
    const float* __restrict__ ew, const float* __restrict__ em) {
    unsigned g = blockIdx.x * 256u + threadIdx.x;
    if (g >= NE / 4) return;
    int4   s = __ldg(reinterpret_cast<const int4*>(src) + g);
    int4   d = __ldg(reinterpret_cast<const int4*>(dst) + g);
    float4 w = __ldg(reinterpret_cast<const float4*>(ew) + g);
    float4 m = __ldg(reinterpret_cast<const float4*>(em) + g);
    int p0 = atomicAdd(&g_cur[d.x], 1);
    int p1 = atomicAdd(&g_cur[d.y], 1);
    int p2 = atomicAdd(&g_cur[d.z], 1);
    int p3 = atomicAdd(&g_cur[d.w], 1);
    g_edata[p0] = ((ull)(unsigned)__float_as_int(w.x * m.x) << 32) | (unsigned)s.x;
    g_edata[p1] = ((ull)(unsigned)__float_as_int(w.y * m.y) << 32) | (unsigned)s.y;
    g_edata[p2] = ((ull)(unsigned)__float_as_int(w.z * m.z) << 32) | (unsigned)s.z;
    g_edata[p3] = ((ull)(unsigned)__float_as_int(w.w * m.w) << 32) | (unsigned)s.w;
}

// Fused gather-mean + dual GEMM. 32 nodes/block, 256 threads, 48KB static smem.
// Gather: 8 threads/node, per-thread chains (high MLP). GEMM: FFMA2 packed cols.
__global__ void __launch_bounds__(256) fused_kernel(
    const float* __restrict__ feat,
    const float* __restrict__ Ws, const float* __restrict__ bs,
    const float* __restrict__ Wn, const float* __restrict__ bn,
    float* __restrict__ out) {
    __shared__ float sWs[DD * DD];      // 16KB, k-major + XOR swizzle
    __shared__ float sWn[DD * DD];      // 16KB
    __shared__ float sA[32 * DD];       // 8KB, row-major
    __shared__ float sB[32 * DD];       // 8KB

    int t = threadIdx.x;
    int base = blockIdx.x * 32;   // 3125*32 = 100000 exact, no guards

    // W fill (transposed + XOR swizzle): W[j][k] -> sW[k*64 + ((j>>2)^(k&15))*4 + (j&3)]
    for (int i = t; i < DD * DD; i += 256) {
        int k = i & 63;
        int j = i >> 6;
        int sidx = k * 64 + (((j >> 2) ^ (k & 15)) << 2) + (j & 3);
        sWs[sidx] = Ws[i];
        sWn[sidx] = Wn[i];
    }

    // stage feat rows (row-major) for the self term
    for (int i = t; i < 32 * 16; i += 256) {
        reinterpret_cast<float4*>(sA)[i] =
            __ldg(reinterpret_cast<const float4*>(feat) + (size_t)base * 16 + i);
    }

    // Phase A: gather. 8 threads/node, lane chunk l8: float4 pair (l8, 8+l8).
    // Per-thread dependent chain only on acc; loads unrolled -> MLP ~4.
    {
        int nl = t >> 3;          // local node 0..31
        int l8 = t & 7;
        int node = base + nl;
        int beg = g_off[node];
        int cnt = g_count[node];
        ull a0x = 0, a0y = 0, a1x = 0, a1y = 0;   // 4 packed f32x2 accs
        const ulonglong2* f16 = reinterpret_cast<const ulonglong2*>(feat);
        #pragma unroll 2
        for (int i2 = 0; i2 < cnt; i2++) {
            ull ed = __ldg((const ull*)g_edata + beg + i2);
            int s = (int)(unsigned)(ed & 0xffffffffull);
            float wgt = __int_as_float((int)(ed >> 32));
            ull w2 = pk(wgt, wgt);
            ulonglong2 f0 = __ldg(f16 + (size_t)s * 16 + l8);      // 16 chunks/row
            ulonglong2 f1 = __ldg(f16 + (size_t)s * 16 + 8 + l8);
            fma2(a0x, f0.x, w2); fma2(a0y, f0.y, w2);
            fma2(a1x, f1.x, w2); fma2(a1y, f1.y, w2);
        }
        float inv = 1.0f / fmaxf((float)cnt, 1.0f);
        ull iv = pk(inv, inv);
        a0x = mul2(a0x, iv); a0y = mul2(a0y, iv);
        a1x = mul2(a1x, iv); a1y = mul2(a1y, iv);
        ull* sB_u = reinterpret_cast<ull*>(sB);
        sB_u[(nl * 16 + l8) * 2 + 0] = a0x;
        sB_u[(nl * 16 + l8) * 2 + 1] = a0y;
        sB_u[(nl * 16 + 8 + l8) * 2 + 0] = a1x;
        sB_u[(nl * 16 + 8 + l8) * 2 + 1] = a1y;
    }
    __syncthreads();

    // Phase B: dual GEMM, FFMA2. thread = 2 nodes x 4 cols (packed as 2x f32x2).
    int jg = t & 15;     // col group: cols 4jg..4jg+3
    int ng = t >> 4;     // node pair: nodes 2ng, 2ng+1
    int j0 = jg * 4;

    ull bias01 = pk(__ldg(bs + j0 + 0) + __ldg(bn + j0 + 0),
                    __ldg(bs + j0 + 1) + __ldg(bn + j0 + 1));
    ull bias23 = pk(__ldg(bs + j0 + 2) + __ldg(bn + j0 + 2),
                    __ldg(bs + j0 + 3) + __ldg(bn + j0 + 3));
    ull acc0_01 = bias01, acc0_23 = bias23;
    ull acc1_01 = bias01, acc1_23 = bias23;

    const float* pA = sA + ng * 128;   // nodes 2ng, 2ng+1 rows
    const float* pB = sB + ng * 128;

    #pragma unroll 16
    for (int k = 0; k < 64; k++) {
        int sw = (jg ^ (k & 15)) << 2;
        ull w01, w23, u01, u23;
        lds2u64(w01, w23, sWs + k * 64 + sw);
        lds2u64(u01, u23, sWn + k * 64 + sw);
        float a0 = pA[k], a1 = pA[64 + k];       // broadcast LDS
        float b0 = pB[k], b1 = pB[64 + k];
        ull sa0 = pk(a0, a0), sa1 = pk(a1, a1);
        ull sb0 = pk(b0, b0), sb1 = pk(b1, b1);
        fma2(acc0_01, sa0, w01); fma2(acc0_23, sa0, w23);
        fma2(acc0_01, sb0, u01); fma2(acc0_23, sb0, u23);
        fma2(acc1_01, sa1, w01); fma2(acc1_23, sa1, w23);
        fma2(acc1_01, sb1, u01); fma2(acc1_23, sb1, u23);
    }

    int n0 = base + 2 * ng;
    float4 o;
    unpk(o.x, o.y, acc0_01); unpk(o.z, o.w, acc0_23);
    reinterpret_cast<float4*>(out)[(size_t)n0 * 16 + jg] = o;
    unpk(o.x, o.y, acc1_01); unpk(o.z, o.w, acc1_23);
    reinterpret_cast<float4*>(out)[(size_t)(n0 + 1) * 16 + jg] = o;
}

extern "C" void kernel_launch(void* const* d_in, const int* in_sizes, int n_in,
                              void* d_out, int out_size) {
    const float* feat = (const float*)d_in[0];
    const int*   src  = (const int*)d_in[1];
    const int*   dst  = (const int*)d_in[2];
    const float* ew   = (const float*)d_in[3];
    const float* em   = (const float*)d_in[4];
    const float* Ws   = (const float*)d_in[5];
    const float* bs   = (const float*)d_in[6];
    const float* Wn   = (const float*)d_in[7];
    const float* bn   = (const float*)d_in[8];
    float* out = (float*)d_out;

    zero_kernel<<<NBLK, 256>>>();
    hist_kernel<<<1172, 256>>>(dst);                 // NE/4 = 300000 threads
    offsets_kernel<<<NBLK, 256>>>();
    fill_kernel<<<1172, 256>>>(src, dst, ew, em);
    fused_kernel<<<GRID_FUSED, 256>>>(feat, Ws, bs, Wn, bn, out);
}

// round 6
// speedup vs baseline: 1.2129x; 1.0156x over previous
#include <cuda_runtime.h>

#define NN 100000
#define NE 1200000
#define DD 64
#define NBLK 391          // ceil(NN/256)
#define GRID_FUSED 3125   // NN/32 exact

typedef unsigned long long ull;

// scratch (__device__ globals per allocation rules)
__device__ int g_count[NN];
__device__ int g_off[NN];
__device__ int g_rank[NE];      // per-edge rank within its dst node
__device__ ull g_edata[NE];     // packed {w_bits, src}
__device__ int g_total;

// ---- f32x2 helpers (sm_103a packed fp32) ----
__device__ __forceinline__ ull pk(float lo, float hi) {
    ull r; asm("mov.b64 %0, {%1, %2};" : "=l"(r) : "f"(lo), "f"(hi)); return r;
}
__device__ __forceinline__ void unpk(float& lo, float& hi, ull v) {
    asm("mov.b64 {%0, %1}, %2;" : "=f"(lo), "=f"(hi) : "l"(v));
}
__device__ __forceinline__ void fma2(ull& d, ull a, ull b) {
    asm("fma.rn.f32x2 %0, %1, %2, %0;" : "+l"(d) : "l"(a), "l"(b));
}
__device__ __forceinline__ ull mul2(ull a, ull b) {
    ull r; asm("mul.rn.f32x2 %0, %1, %2;" : "=l"(r) : "l"(a), "l"(b)); return r;
}
__device__ __forceinline__ void lds2u64(ull& a, ull& b, const float* p) {
    unsigned ad = (unsigned)__cvta_generic_to_shared(p);
    asm volatile("ld.shared.v2.u64 {%0, %1}, [%2];" : "=l"(a), "=l"(b) : "r"(ad));
}

__global__ void __launch_bounds__(256) zero_kernel() {
    int i = blockIdx.x * 256 + threadIdx.x;
    if (i < NN) g_count[i] = 0;
    if (i == 0) g_total = 0;
}

// 4 edges/thread: histogram with returned rank, stored coalesced.
__global__ void __launch_bounds__(256) hist_kernel(const int* __restrict__ dst) {
    unsigned g = blockIdx.x * 256u + threadIdx.x;
    if (g >= NE / 4) return;
    int4 d = __ldg(reinterpret_cast<const int4*>(dst) + g);
    int4 r;
    r.x = atomicAdd(&g_count[d.x], 1);
    r.y = atomicAdd(&g_count[d.y], 1);
    r.z = atomicAdd(&g_count[d.z], 1);
    r.w = atomicAdd(&g_count[d.w], 1);
    reinterpret_cast<int4*>(g_rank)[g] = r;
}

// Block-local scan + one global atomicAdd for the base.
__global__ void __launch_bounds__(256) offsets_kernel() {
    __shared__ int arr[256];
    __shared__ int sBase;
    int t = threadIdx.x;
    int i = blockIdx.x * 256 + t;
    int c = (i < NN) ? g_count[i] : 0;
    arr[t] = c;
    __syncthreads();
    #pragma unroll
    for (int off = 1; off < 256; off <<= 1) {
        int v = (t >= off) ? arr[t - off] : 0;
        __syncthreads();
        arr[t] += v;
        __syncthreads();
    }
    if (t == 255) sBase = atomicAdd(&g_total, arr[255]);
    __syncthreads();
    if (i < NN) g_off[i] = sBase + arr[t] - c;   // exclusive
}

// Atomic-free fill: pos = g_off[dst] + precomputed rank. 4 edges/thread.
__global__ void __launch_bounds__(256) fill_kernel(
    const int* __restrict__ src, const int* __restrict__ dst,
    const float* __restrict__ ew, const float* __restrict__ em) {
    unsigned g = blockIdx.x * 256u + threadIdx.x;
    if (g >= NE / 4) return;
    int4   s = __ldg(reinterpret_cast<const int4*>(src) + g);
    int4   d = __ldg(reinterpret_cast<const int4*>(dst) + g);
    int4   r = reinterpret_cast<const int4*>(g_rank)[g];
    float4 w = __ldg(reinterpret_cast<const float4*>(ew) + g);
    float4 m = __ldg(reinterpret_cast<const float4*>(em) + g);
    int p0 = g_off[d.x] + r.x;
    int p1 = g_off[d.y] + r.y;
    int p2 = g_off[d.z] + r.z;
    int p3 = g_off[d.w] + r.w;
    g_edata[p0] = ((ull)(unsigned)__float_as_int(w.x * m.x) << 32) | (unsigned)s.x;
    g_edata[p1] = ((ull)(unsigned)__float_as_int(w.y * m.y) << 32) | (unsigned)s.y;
    g_edata[p2] = ((ull)(unsigned)__float_as_int(w.z * m.z) << 32) | (unsigned)s.z;
    g_edata[p3] = ((ull)(unsigned)__float_as_int(w.w * m.w) << 32) | (unsigned)s.w;
}

// Fused gather-mean + dual GEMM. 32 nodes/block, 256 threads, 48KB static smem.
__global__ void __launch_bounds__(256) fused_kernel(
    const float* __restrict__ feat,
    const float* __restrict__ Ws, const float* __restrict__ bs,
    const float* __restrict__ Wn, const float* __restrict__ bn,
    float* __restrict__ out) {
    __shared__ float sWs[DD * DD];      // 16KB, k-major + XOR swizzle
    __shared__ float sWn[DD * DD];      // 16KB
    __shared__ float sA[32 * DD];       // 8KB, row-major
    __shared__ float sB[32 * DD];       // 8KB

    int t = threadIdx.x;
    int base = blockIdx.x * 32;   // 3125*32 = 100000 exact

    // W fill (transposed + XOR swizzle): W[j][k] -> sW[k*64 + ((j>>2)^(k&15))*4 + (j&3)]
    for (int i = t; i < DD * DD; i += 256) {
        int k = i & 63;
        int j = i >> 6;
        int sidx = k * 64 + (((j >> 2) ^ (k & 15)) << 2) + (j & 3);
        sWs[sidx] = Ws[i];
        sWn[sidx] = Wn[i];
    }

    // stage feat rows (row-major) for the self term
    for (int i = t; i < 32 * 16; i += 256) {
        reinterpret_cast<float4*>(sA)[i] =
            __ldg(reinterpret_cast<const float4*>(feat) + (size_t)base * 16 + i);
    }

    // Phase A: gather. 8 threads/node, per-thread acc chains, deep unroll.
    {
        int nl = t >> 3;          // local node 0..31
        int l8 = t & 7;
        int node = base + nl;
        int beg = g_off[node];
        int cnt = g_count[node];
        ull a0x = 0, a0y = 0, a1x = 0, a1y = 0;
        const ulonglong2* f16 = reinterpret_cast<const ulonglong2*>(feat);
        #pragma unroll 4
        for (int i2 = 0; i2 < cnt; i2++) {
            ull ed = __ldg((const ull*)g_edata + beg + i2);
            int s = (int)(unsigned)(ed & 0xffffffffull);
            float wgt = __int_as_float((int)(ed >> 32));
            ull w2 = pk(wgt, wgt);
            ulonglong2 f0 = __ldg(f16 + (size_t)s * 16 + l8);
            ulonglong2 f1 = __ldg(f16 + (size_t)s * 16 + 8 + l8);
            fma2(a0x, f0.x, w2); fma2(a0y, f0.y, w2);
            fma2(a1x, f1.x, w2); fma2(a1y, f1.y, w2);
        }
        float inv = 1.0f / fmaxf((float)cnt, 1.0f);
        ull iv = pk(inv, inv);
        a0x = mul2(a0x, iv); a0y = mul2(a0y, iv);
        a1x = mul2(a1x, iv); a1y = mul2(a1y, iv);
        ull* sB_u = reinterpret_cast<ull*>(sB);
        sB_u[(nl * 16 + l8) * 2 + 0] = a0x;
        sB_u[(nl * 16 + l8) * 2 + 1] = a0y;
        sB_u[(nl * 16 + 8 + l8) * 2 + 0] = a1x;
        sB_u[(nl * 16 + 8 + l8) * 2 + 1] = a1y;
    }
    __syncthreads();

    // Phase B: dual GEMM, FFMA2. thread = 2 nodes x 4 cols.
    int jg = t & 15;
    int ng = t >> 4;
    int j0 = jg * 4;

    ull bias01 = pk(__ldg(bs + j0 + 0) + __ldg(bn + j0 + 0),
                    __ldg(bs + j0 + 1) + __ldg(bn + j0 + 1));
    ull bias23 = pk(__ldg(bs + j0 + 2) + __ldg(bn + j0 + 2),
                    __ldg(bs + j0 + 3) + __ldg(bn + j0 + 3));
    ull acc0_01 = bias01, acc0_23 = bias23;
    ull acc1_01 = bias01, acc1_23 = bias23;

    const float* pA = sA + ng * 128;
    const float* pB = sB + ng * 128;

    #pragma unroll 16
    for (int k = 0; k < 64; k++) {
        int sw = (jg ^ (k & 15)) << 2;
        ull w01, w23, u01, u23;
        lds2u64(w01, w23, sWs + k * 64 + sw);
        lds2u64(u01, u23, sWn + k * 64 + sw);
        float a0 = pA[k], a1 = pA[64 + k];
        float b0 = pB[k], b1 = pB[64 + k];
        ull sa0 = pk(a0, a0), sa1 = pk(a1, a1);
        ull sb0 = pk(b0, b0), sb1 = pk(b1, b1);
        fma2(acc0_01, sa0, w01); fma2(acc0_23, sa0, w23);
        fma2(acc0_01, sb0, u01); fma2(acc0_23, sb0, u23);
        fma2(acc1_01, sa1, w01); fma2(acc1_23, sa1, w23);
        fma2(acc1_01, sb1, u01); fma2(acc1_23, sb1, u23);
    }

    int n0 = base + 2 * ng;
    float4 o;
    unpk(o.x, o.y, acc0_01); unpk(o.z, o.w, acc0_23);
    reinterpret_cast<float4*>(out)[(size_t)n0 * 16 + jg] = o;
    unpk(o.x, o.y, acc1_01); unpk(o.z, o.w, acc1_23);
    reinterpret_cast<float4*>(out)[(size_t)(n0 + 1) * 16 + jg] = o;
}

extern "C" void kernel_launch(void* const* d_in, const int* in_sizes, int n_in,
                              void* d_out, int out_size) {
    const float* feat = (const float*)d_in[0];
    const int*   src  = (const int*)d_in[1];
    const int*   dst  = (const int*)d_in[2];
    const float* ew   = (const float*)d_in[3];
    const float* em   = (const float*)d_in[4];
    const float* Ws   = (const float*)d_in[5];
    const float* bs   = (const float*)d_in[6];
    const float* Wn   = (const float*)d_in[7];
    const float* bn   = (const float*)d_in[8];
    float* out = (float*)d_out;

    zero_kernel<<<NBLK, 256>>>();
    hist_kernel<<<1172, 256>>>(dst);                 // NE/4 threads
    offsets_kernel<<<NBLK, 256>>>();
    fill_kernel<<<1172, 256>>>(src, dst, ew, em);
    fused_kernel<<<GRID_FUSED, 256>>>(feat, Ws, bs, Wn, bn, out);
}

// round 7
// speedup vs baseline: 1.2327x; 1.0163x over previous
#include <cuda_runtime.h>

#define NN 100000
#define NE 1200000
#define DD 64
#define NBLK 391          // ceil(NN/256)
#define GRID_FUSED 3125   // NN/32 exact
#define OFFMASK 0x1FFFFFu

typedef unsigned long long ull;

// scratch (__device__ globals per allocation rules; zero-initialized at load)
__device__ int      g_count[NN];
__device__ unsigned g_offcnt[NN];    // off | (cnt<<21)
__device__ int      g_rank[NE];      // per-edge rank within its dst node
__device__ ull      g_edata[NE];     // packed {w_bits, src}
__device__ int      g_total;

// ---- f32x2 helpers (sm_103a packed fp32) ----
__device__ __forceinline__ ull pk(float lo, float hi) {
    ull r; asm("mov.b64 %0, {%1, %2};" : "=l"(r) : "f"(lo), "f"(hi)); return r;
}
__device__ __forceinline__ void unpk(float& lo, float& hi, ull v) {
    asm("mov.b64 {%0, %1}, %2;" : "=f"(lo), "=f"(hi) : "l"(v));
}
__device__ __forceinline__ void fma2(ull& d, ull a, ull b) {
    asm("fma.rn.f32x2 %0, %1, %2, %0;" : "+l"(d) : "l"(a), "l"(b));
}
__device__ __forceinline__ ull mul2(ull a, ull b) {
    ull r; asm("mul.rn.f32x2 %0, %1, %2;" : "=l"(r) : "l"(a), "l"(b)); return r;
}
__device__ __forceinline__ void lds2u64(ull& a, ull& b, const float* p) {
    unsigned ad = (unsigned)__cvta_generic_to_shared(p);
    asm volatile("ld.shared.v2.u64 {%0, %1}, [%2];" : "=l"(a), "=l"(b) : "r"(ad));
}

// Launch 1: histogram (counts were zeroed by previous offsets run / static init),
// record per-edge rank, reset g_total for this call's offsets pass.
__global__ void __launch_bounds__(256) hist_kernel(const int* __restrict__ dst) {
    unsigned g = blockIdx.x * 256u + threadIdx.x;
    if (g == 0) g_total = 0;
    if (g >= NE / 4) return;
    int4 d = __ldg(reinterpret_cast<const int4*>(dst) + g);
    int4 r;
    r.x = atomicAdd(&g_count[d.x], 1);
    r.y = atomicAdd(&g_count[d.y], 1);
    r.z = atomicAdd(&g_count[d.z], 1);
    r.w = atomicAdd(&g_count[d.w], 1);
    reinterpret_cast<int4*>(g_rank)[g] = r;
}

// Launch 2: block-local scan + one global atomicAdd base; writes packed
// off|cnt and re-zeros g_count for the next call (graph-replay invariant).
__global__ void __launch_bounds__(256) offsets_kernel() {
    __shared__ int arr[256];
    __shared__ int sBase;
    int t = threadIdx.x;
    int i = blockIdx.x * 256 + t;
    int c = (i < NN) ? g_count[i] : 0;
    arr[t] = c;
    __syncthreads();
    #pragma unroll
    for (int off = 1; off < 256; off <<= 1) {
        int v = (t >= off) ? arr[t - off] : 0;
        __syncthreads();
        arr[t] += v;
        __syncthreads();
    }
    if (t == 255) sBase = atomicAdd(&g_total, arr[255]);
    __syncthreads();
    if (i < NN) {
        g_offcnt[i] = (unsigned)(sBase + arr[t] - c) | ((unsigned)c << 21);
        g_count[i] = 0;
    }
}

// Launch 3: atomic-free fill. pos = off(dst) + rank. 4 edges/thread.
__global__ void __launch_bounds__(256) fill_kernel(
    const int* __restrict__ src, const int* __restrict__ dst,
    const float* __restrict__ ew, const float* __restrict__ em) {
    unsigned g = blockIdx.x * 256u + threadIdx.x;
    if (g >= NE / 4) return;
    int4   s = __ldg(reinterpret_cast<const int4*>(src) + g);
    int4   d = __ldg(reinterpret_cast<const int4*>(dst) + g);
    int4   r = reinterpret_cast<const int4*>(g_rank)[g];
    float4 w = __ldg(reinterpret_cast<const float4*>(ew) + g);
    float4 m = __ldg(reinterpret_cast<const float4*>(em) + g);
    int p0 = (int)(g_offcnt[d.x] & OFFMASK) + r.x;
    int p1 = (int)(g_offcnt[d.y] & OFFMASK) + r.y;
    int p2 = (int)(g_offcnt[d.z] & OFFMASK) + r.z;
    int p3 = (int)(g_offcnt[d.w] & OFFMASK) + r.w;
    g_edata[p0] = ((ull)(unsigned)__float_as_int(w.x * m.x) << 32) | (unsigned)s.x;
    g_edata[p1] = ((ull)(unsigned)__float_as_int(w.y * m.y) << 32) | (unsigned)s.y;
    g_edata[p2] = ((ull)(unsigned)__float_as_int(w.z * m.z) << 32) | (unsigned)s.z;
    g_edata[p3] = ((ull)(unsigned)__float_as_int(w.w * m.w) << 32) | (unsigned)s.w;
}

// Launch 4 (profiled): fused gather-mean + dual GEMM. 32 nodes/block,
// 256 threads, 48KB static smem.
__global__ void __launch_bounds__(256) fused_kernel(
    const float* __restrict__ feat,
    const float* __restrict__ Ws, const float* __restrict__ bs,
    const float* __restrict__ Wn, const float* __restrict__ bn,
    float* __restrict__ out) {
    __shared__ float sWs[DD * DD];      // 16KB, k-major + XOR swizzle
    __shared__ float sWn[DD * DD];      // 16KB
    __shared__ float sA[32 * DD];       // 8KB, row-major
    __shared__ float sB[32 * DD];       // 8KB

    int t = threadIdx.x;
    int base = blockIdx.x * 32;   // 3125*32 = 100000 exact

    // W fill (transposed + XOR swizzle): W[j][k] -> sW[k*64 + ((j>>2)^(k&15))*4 + (j&3)]
    for (int i = t; i < DD * DD; i += 256) {
        int k = i & 63;
        int j = i >> 6;
        int sidx = k * 64 + (((j >> 2) ^ (k & 15)) << 2) + (j & 3);
        sWs[sidx] = Ws[i];
        sWn[sidx] = Wn[i];
    }

    // stage feat rows (row-major) for the self term
    for (int i = t; i < 32 * 16; i += 256) {
        reinterpret_cast<float4*>(sA)[i] =
            __ldg(reinterpret_cast<const float4*>(feat) + (size_t)base * 16 + i);
    }

    // Phase A: gather. 8 threads/node, per-thread acc chains, deep unroll.
    {
        int nl = t >> 3;          // local node 0..31
        int l8 = t & 7;
        unsigned oc = g_offcnt[base + nl];
        int beg = (int)(oc & OFFMASK);
        int cnt = (int)(oc >> 21);
        ull a0x = 0, a0y = 0, a1x = 0, a1y = 0;
        const ulonglong2* f16 = reinterpret_cast<const ulonglong2*>(feat);
        #pragma unroll 4
        for (int i2 = 0; i2 < cnt; i2++) {
            ull ed = __ldg((const ull*)g_edata + beg + i2);
            int s = (int)(unsigned)(ed & 0xffffffffull);
            float wgt = __int_as_float((int)(ed >> 32));
            ull w2 = pk(wgt, wgt);
            ulonglong2 f0 = __ldg(f16 + (size_t)s * 16 + l8);
            ulonglong2 f1 = __ldg(f16 + (size_t)s * 16 + 8 + l8);
            fma2(a0x, f0.x, w2); fma2(a0y, f0.y, w2);
            fma2(a1x, f1.x, w2); fma2(a1y, f1.y, w2);
        }
        float inv = 1.0f / fmaxf((float)cnt, 1.0f);
        ull iv = pk(inv, inv);
        a0x = mul2(a0x, iv); a0y = mul2(a0y, iv);
        a1x = mul2(a1x, iv); a1y = mul2(a1y, iv);
        ull* sB_u = reinterpret_cast<ull*>(sB);
        sB_u[(nl * 16 + l8) * 2 + 0] = a0x;
        sB_u[(nl * 16 + l8) * 2 + 1] = a0y;
        sB_u[(nl * 16 + 8 + l8) * 2 + 0] = a1x;
        sB_u[(nl * 16 + 8 + l8) * 2 + 1] = a1y;
    }
    __syncthreads();

    // Phase B: dual GEMM, FFMA2. thread = 2 nodes x 4 cols.
    int jg = t & 15;
    int ng = t >> 4;
    int j0 = jg * 4;

    ull bias01 = pk(__ldg(bs + j0 + 0) + __ldg(bn + j0 + 0),
                    __ldg(bs + j0 + 1) + __ldg(bn + j0 + 1));
    ull bias23 = pk(__ldg(bs + j0 + 2) + __ldg(bn + j0 + 2),
                    __ldg(bs + j0 + 3) + __ldg(bn + j0 + 3));
    ull acc0_01 = bias01, acc0_23 = bias23;
    ull acc1_01 = bias01, acc1_23 = bias23;

    const float* pA = sA + ng * 128;
    const float* pB = sB + ng * 128;

    #pragma unroll 16
    for (int k = 0; k < 64; k++) {
        int sw = (jg ^ (k & 15)) << 2;
        ull w01, w23, u01, u23;
        lds2u64(w01, w23, sWs + k * 64 + sw);
        lds2u64(u01, u23, sWn + k * 64 + sw);
        float a0 = pA[k], a1 = pA[64 + k];
        float b0 = pB[k], b1 = pB[64 + k];
        ull sa0 = pk(a0, a0), sa1 = pk(a1, a1);
        ull sb0 = pk(b0, b0), sb1 = pk(b1, b1);
        fma2(acc0_01, sa0, w01); fma2(acc0_23, sa0, w23);
        fma2(acc0_01, sb0, u01); fma2(acc0_23, sb0, u23);
        fma2(acc1_01, sa1, w01); fma2(acc1_23, sa1, w23);
        fma2(acc1_01, sb1, u01); fma2(acc1_23, sb1, u23);
    }

    int n0 = base + 2 * ng;
    float4 o;
    unpk(o.x, o.y, acc0_01); unpk(o.z, o.w, acc0_23);
    reinterpret_cast<float4*>(out)[(size_t)n0 * 16 + jg] = o;
    unpk(o.x, o.y, acc1_01); unpk(o.z, o.w, acc1_23);
    reinterpret_cast<float4*>(out)[(size_t)(n0 + 1) * 16 + jg] = o;
}

extern "C" void kernel_launch(void* const* d_in, const int* in_sizes, int n_in,
                              void* d_out, int out_size) {
    const float* feat = (const float*)d_in[0];
    const int*   src  = (const int*)d_in[1];
    const int*   dst  = (const int*)d_in[2];
    const float* ew   = (const float*)d_in[3];
    const float* em   = (const float*)d_in[4];
    const float* Ws   = (const float*)d_in[5];
    const float* bs   = (const float*)d_in[6];
    const float* Wn   = (const float*)d_in[7];
    const float* bn   = (const float*)d_in[8];
    float* out = (float*)d_out;

    hist_kernel<<<1172, 256>>>(dst);                 // NE/4 threads
    offsets_kernel<<<NBLK, 256>>>();
    fill_kernel<<<1172, 256>>>(src, dst, ew, em);
    fused_kernel<<<GRID_FUSED, 256>>>(feat, Ws, bs, Wn, bn, out);
}